// round 13
// baseline (speedup 1.0000x reference)
#include <cuda_runtime.h>
#include <cuda_bf16.h>
#include <math.h>

#define N_NODES 1024
#define IN_F    256
#define OUT_F   128   // H*NH
#define TI      8     // target nodes per i-group
#define JHALF   512   // source nodes per block

// GL4[f][j] = float4 over heads (gl[j][hh*32+f], hh=0..3); row 32 = pad
__device__ float4 GL4[33 * N_NODES];
// GRD[opair][j] = (gr[2p][j], gr[2p+1][j])
__device__ float2 GRD[64 * N_NODES];
// gr natural layout [j][o]
__device__ float GRN[N_NODES * OUT_F];
// partial aggregation scratch
__device__ float PNUM[256][1024];
__device__ float PDEN[256][32];

// ---------------------------------------------------------------------------
// Packed fp32x2 helpers
// ---------------------------------------------------------------------------
__device__ __forceinline__ float2 fadd2(float2 a, float2 b) {
    float2 r;
    asm("add.rn.f32x2 %0, %1, %2;"
        : "=l"(*(unsigned long long*)&r)
        : "l"(*(const unsigned long long*)&a),
          "l"(*(const unsigned long long*)&b));
    return r;
}
__device__ __forceinline__ float2 ffma2(float2 a, float2 b, float2 c) {
    float2 r;
    asm("fma.rn.f32x2 %0, %1, %2, %3;"
        : "=l"(*(unsigned long long*)&r)
        : "l"(*(const unsigned long long*)&a),
          "l"(*(const unsigned long long*)&b),
          "l"(*(const unsigned long long*)&c));
    return r;
}
__device__ __forceinline__ float2 pack2(float x, float y) {
    float2 r;
    asm("mov.b64 %0, {%1, %2};"
        : "=l"(*(unsigned long long*)&r) : "f"(x), "f"(y));
    return r;
}

// ---------------------------------------------------------------------------
// Kernel A: tiled GEMM. grid (32 j-chunks, 8 o-groups) = 256 blocks, 256 thr.
// Tile = 32 j x 32 o-slots, k chunks of 64, register double-buffered.
// Thread = (o-pair po, j-pair jh). Inner k: 2x LDS.64 (hv is warp-broadcast),
// 2x FFMA2. o-groups 0..3 -> gl (permuted W rows: 8 f x 4 hh); 4..7 -> gr.
// ---------------------------------------------------------------------------
#define WS2 34
#define SS2 33

__global__ void __launch_bounds__(256) gat_gemm(
    const float* __restrict__ h,
    const float* __restrict__ Wl,
    const float* __restrict__ Wr)
{
    __shared__ float hs[64 * WS2];   // [k][j_loc slot]
    __shared__ float ws[64 * WS2];   // [k][o slot]

    const int t  = threadIdx.x;
    const int bx = blockIdx.x;             // j-chunk (0..31)
    const int by = blockIdx.y;             // o-group (0..7)
    const int j0 = bx * 32;
    const bool is_gl = (by < 4);

    // compute-role: o-pair and j-pair
    const int po = t & 15;                 // o slots {2po, 2po+1}
    const int jh = t >> 4;                 // j_loc {2jh, 2jh+1}

    // load-role: slot ls (0..31), k-offset lk (8 floats)
    const int ls = t >> 3;
    const int lk = (t & 7) * 8;

    int wrow;
    const float* __restrict__ Wsrc;
    if (is_gl) { wrow = ((ls >> 3) << 5) + (by << 3) + (ls & 7); Wsrc = Wl; }
    else       { wrow = ((by - 4) << 5) + ls;                    Wsrc = Wr; }
    const float* __restrict__ wptr = Wsrc + wrow * IN_F + lk;
    const float* __restrict__ hptr = h + (j0 + ls) * IN_F + lk;

    float rw[8], rh[8];
#pragma unroll
    for (int u = 0; u < 2; u++) *(float4*)&rw[u * 4] = *(const float4*)&wptr[u * 4];
#pragma unroll
    for (int u = 0; u < 2; u++) *(float4*)&rh[u * 4] = *(const float4*)&hptr[u * 4];

    float2 acc0 = make_float2(0.f, 0.f);   // j = 2jh
    float2 acc1 = make_float2(0.f, 0.f);   // j = 2jh+1

    for (int c = 0; c < 4; c++) {
        __syncthreads();
#pragma unroll
        for (int u = 0; u < 8; u++) {
            ws[(lk + u) * WS2 + ls] = rw[u];
            hs[(lk + u) * WS2 + ls] = rh[u];
        }
        __syncthreads();
        if (c < 3) {
            const float* wn = wptr + (c + 1) * 64;
            const float* hn = hptr + (c + 1) * 64;
#pragma unroll
            for (int u = 0; u < 2; u++) *(float4*)&rw[u * 4] = *(const float4*)&wn[u * 4];
#pragma unroll
            for (int u = 0; u < 2; u++) *(float4*)&rh[u * 4] = *(const float4*)&hn[u * 4];
        }
#pragma unroll 16
        for (int k = 0; k < 64; k++) {
            float2 wv = *(const float2*)&ws[k * WS2 + 2 * po];   // 16 addrs, dedup
            float2 hv = *(const float2*)&hs[k * WS2 + 2 * jh];   // warp-broadcast
            acc0 = ffma2(pack2(hv.x, hv.x), wv, acc0);
            acc1 = ffma2(pack2(hv.y, hv.y), wv, acc1);
        }
    }

    if (is_gl) {
        // stage [slot][j_loc] then emit GL4 float4 over hh (coalesced)
        __syncthreads();
        hs[(2 * po    ) * SS2 + 2 * jh    ] = acc0.x;
        hs[(2 * po + 1) * SS2 + 2 * jh    ] = acc0.y;
        hs[(2 * po    ) * SS2 + 2 * jh + 1] = acc1.x;
        hs[(2 * po + 1) * SS2 + 2 * jh + 1] = acc1.y;
        __syncthreads();
        const int fl = t >> 5, jl = t & 31;      // fl 0..7, jl 0..31
        float4 g;
        g.x = hs[( 0 + fl) * SS2 + jl];
        g.y = hs[( 8 + fl) * SS2 + jl];
        g.z = hs[(16 + fl) * SS2 + jl];
        g.w = hs[(24 + fl) * SS2 + jl];
        GL4[(((by << 3) + fl) << 10) + j0 + jl] = g;
    } else {
        const int og0 = (by - 4) << 5;
        const int pg  = (og0 >> 1) + po;         // global o-pair index
        const int j   = j0 + 2 * jh;
        *(float2*)&GRN[( j      << 7) + og0 + 2 * po] = acc0;
        *(float2*)&GRN[((j + 1) << 7) + og0 + 2 * po] = acc1;
        GRD[(pg << 10) + j    ] = acc0;
        GRD[(pg << 10) + j + 1] = acc1;
    }
}

// ---------------------------------------------------------------------------
// Kernel B: grid (2 j-halves, 128 i-groups), 1024 threads.
// Thread = (j, f-half); f-halves share a warp (lane halves) and combine via
// shfl.xor(16). Block emits PARTIAL num/den to global scratch (no max-pass
// softmax; partial sums compose exactly).
// ---------------------------------------------------------------------------
#define OFF_GRS  16384
#define OFF_RED  (OFF_GRS + 1024)
#define OFF_DOTR (OFF_RED + 1056)
#define OFF_CW   (OFF_DOTR + 32)
#define SMEM_FLOATS (OFF_CW + 64)

__global__ void __launch_bounds__(1024, 1) gat_main(
    const int*   __restrict__ adj,
    const float* __restrict__ attn_w,
    float*       __restrict__ out_unused)
{
    extern __shared__ float sm[];
    float4* a4     = (float4*)sm;            // 8 rows x 512 float4 (p values)
    float*  grs    = sm + OFF_GRS;           // [o][ii 0..7]
    float*  red    = sm + OFF_RED;           // 32 warps x 33
    float*  dotr_s = sm + OFF_DOTR;          // 32
    float2* cw     = (float2*)(sm + OFF_CW);

    const int t     = threadIdx.x;
    const int lane  = t & 31;
    const int warp  = t >> 5;
    const int jhb   = blockIdx.x;            // j-half
    const int ib    = blockIdx.y;            // i-group
    const int i0    = ib * TI;
    const int jbase = jhb * JHALF;
    const int jl    = lane & 15;
    const int fh    = lane >> 4;             // f-half AND ii-half role
    const int jloc  = (warp << 4) + jl;      // 0..511
    const int j     = jbase + jloc;          // global source node
    const int sidx  = ib * 2 + jhb;

    if (t < 32) { float w = attn_w[t]; cw[t] = make_float2(0.6f * w, 0.4f * w); }
    { int ii = t >> 7, oo = t & 127; grs[(oo << 3) + ii] = GRN[(i0 + ii) * OUT_F + oo]; }

    unsigned am = 0;   // 4 bits for ii in this thread's half
#pragma unroll
    for (int iil = 0; iil < 4; iil++)
        am |= (adj[(i0 + (fh << 2) + iil) * N_NODES + j] != 0) ? (1u << iil) : 0u;
    __syncthreads();

    // warp 0: dotr[ii][hh] = sum_f 0.6*w_f * gr[i0+ii][hh*32+f]
    if (t < 32) {
        int ii = t >> 2, hh = t & 3;
        float s = 0.f;
#pragma unroll 8
        for (int f = 0; f < 32; f++)
            s += cw[f].x * grs[(((hh << 5) + f) << 3) + ii];
        dotr_s[t] = s;   // index q = ii*4 + hh
    }

    // -------- Phase 1: half the f's per thread, all 8 ii --------
    float acc[32];               // [ii*4 + hh]
#pragma unroll
    for (int q = 0; q < 32; q++) acc[q] = 0.f;
    float dl[4] = {0.f, 0.f, 0.f, 0.f};

    const float4* grs4 = (const float4*)grs;
    const int fbase = fh << 4;
    for (int fi = 0; fi < 16; fi++) {
        int f = fbase + fi;
        float4 ga = GL4[(f << 10) + j];
        float2 c = cw[f];
        dl[0] = fmaf(c.x, ga.x, dl[0]);
        dl[1] = fmaf(c.x, ga.y, dl[1]);
        dl[2] = fmaf(c.x, ga.z, dl[2]);
        dl[3] = fmaf(c.x, ga.w, dl[3]);
        float gaa[4] = {ga.x, ga.y, ga.z, ga.w};
#pragma unroll
        for (int hh = 0; hh < 4; hh++) {
            int o = (hh << 5) + f;
            float4 g0 = grs4[o * 2];         // ii 0..3
            float4 g1 = grs4[o * 2 + 1];     // ii 4..7
            float2 gl2 = pack2(gaa[hh], gaa[hh]);
            float2 x01 = fadd2(gl2, pack2(g0.x, g0.y));
            float2 x23 = fadd2(gl2, pack2(g0.z, g0.w));
            float2 x45 = fadd2(gl2, pack2(g1.x, g1.y));
            float2 x67 = fadd2(gl2, pack2(g1.z, g1.w));
            acc[ 0 + hh] = fmaf(c.y, fabsf(x01.x), acc[ 0 + hh]);
            acc[ 4 + hh] = fmaf(c.y, fabsf(x01.y), acc[ 4 + hh]);
            acc[ 8 + hh] = fmaf(c.y, fabsf(x23.x), acc[ 8 + hh]);
            acc[12 + hh] = fmaf(c.y, fabsf(x23.y), acc[12 + hh]);
            acc[16 + hh] = fmaf(c.y, fabsf(x45.x), acc[16 + hh]);
            acc[20 + hh] = fmaf(c.y, fabsf(x45.y), acc[20 + hh]);
            acc[24 + hh] = fmaf(c.y, fabsf(x67.x), acc[24 + hh]);
            acc[28 + hh] = fmaf(c.y, fabsf(x67.y), acc[28 + hh]);
        }
    }
    // combine f-halves: lane l <-> l^16 hold the two partial sums for same j
#pragma unroll
    for (int q = 0; q < 32; q++) acc[q] += __shfl_xor_sync(0xffffffffu, acc[q], 16);
#pragma unroll
    for (int hh = 0; hh < 4; hh++) dl[hh] += __shfl_xor_sync(0xffffffffu, dl[hh], 16);
    __syncthreads();   // dotr_s visible

    // -------- Phase 2: each lane-half finalizes its 4 ii --------
    float p[16];       // [iil*4 + hh], ii = fh*4 + iil
    {
        const int qb = fh << 4;
#pragma unroll
        for (int iil = 0; iil < 4; iil++) {
            bool m = (am >> iil) & 1u;
#pragma unroll
            for (int hh = 0; hh < 4; hh++) {
                float e = acc[qb + iil * 4 + hh] + dl[hh]
                        + dotr_s[(((fh << 2) + iil) << 2) + hh];
                p[iil * 4 + hh] = m ? __expf(e) : 0.f;
            }
        }
        // store p: row = hh*2 + fh, float4 over iil
#pragma unroll
        for (int hh = 0; hh < 4; hh++) {
            float4 v = make_float4(p[hh], p[4 + hh], p[8 + hh], p[12 + hh]);
            a4[(((hh << 1) + fh) << 9) + jloc] = v;
        }
    }
    // partial den: reduce over 16 j within each half-warp
#pragma unroll
    for (int qq = 0; qq < 16; qq++) {
        float v = p[qq];
#pragma unroll
        for (int d = 8; d; d >>= 1) v += __shfl_xor_sync(0xffffffffu, v, d);
        if (jl == 0) red[warp * 33 + (fh << 4) + qq] = v;
    }
    __syncthreads();   // p stores + red complete
    if (t < 32) {
        float s = 0.f;
#pragma unroll
        for (int w8 = 0; w8 < 32; w8++) s += red[w8 * 33 + t];
        PDEN[sidx][t] = s;     // q = ii*4 + hh
    }

    // -------- Phase 3: partial aggregation over this j-half --------
    const int opair = t >> 4;            // 0..63
    const int ihp   = (t >> 3) & 1;      // ii-half
    const int c     = t & 7;             // j-partition
    const int hh3   = opair >> 4;
    float2 accp[4];
#pragma unroll
    for (int v = 0; v < 4; v++) accp[v] = make_float2(0.f, 0.f);

    const float4* prow = a4 + (((hh3 << 1) + ihp) << 9);
    const float2* grp  = GRD + (opair << 10) + jbase;
#pragma unroll 4
    for (int g = 0; g < 64; g++) {
        int jl3 = (g << 3) + c;
        float4 pv = prow[jl3];           // 4 ii of this half
        float2 gr = grp[jl3];            // both o's of the pair
        float2 p01 = make_float2(pv.x, pv.y);
        float2 p23 = make_float2(pv.z, pv.w);
        float2 gx2 = pack2(gr.x, gr.x);
        float2 gy2 = pack2(gr.y, gr.y);
        accp[0] = ffma2(p01, gx2, accp[0]);
        accp[1] = ffma2(p23, gx2, accp[1]);
        accp[2] = ffma2(p01, gy2, accp[2]);
        accp[3] = ffma2(p23, gy2, accp[3]);
    }
    __syncthreads();                     // all a4 reads complete

    float a8[8] = {accp[0].x, accp[0].y, accp[1].x, accp[1].y,
                   accp[2].x, accp[2].y, accp[3].x, accp[3].y};
    float* part = sm;                    // [t][8] padded to 9
#pragma unroll
    for (int v = 0; v < 8; v++) part[t * 9 + v] = a8[v];
    __syncthreads();

    {
        int o2 = t & 127, ii2 = t >> 7;
        int op = o2 >> 1, oi = o2 & 1, ihq = ii2 >> 2, iil = ii2 & 3;
        float s = 0.f;
#pragma unroll
        for (int cc = 0; cc < 8; cc++)
            s += part[((op << 4) + (ihq << 3) + cc) * 9 + (oi << 2) + iil];
        PNUM[sidx][(ii2 << 7) + o2] = s;
    }
}

// ---------------------------------------------------------------------------
// Kernel C: combine the two j-half partials, normalize, ELU, write out.
// ---------------------------------------------------------------------------
__global__ void __launch_bounds__(1024) gat_combine(float* __restrict__ out)
{
    const int b = blockIdx.x;            // i-group
    const int t = threadIdx.x;
    const int ii2 = t >> 7, o2 = t & 127;
    float num = PNUM[b * 2][t] + PNUM[b * 2 + 1][t];
    int q = (ii2 << 2) + (o2 >> 5);
    float den = PDEN[b * 2][q] + PDEN[b * 2 + 1][q];
    float s = num / den;
    out[(b * TI + ii2) * OUT_F + o2] = (s > 0.f) ? s : expm1f(s);
}

// ---------------------------------------------------------------------------
extern "C" void kernel_launch(void* const* d_in, const int* in_sizes, int n_in,
                              void* d_out, int out_size)
{
    const float* h    = (const float*)d_in[0];
    const int*   adj  = (const int*)  d_in[1];
    const float* Wl   = (const float*)d_in[2];
    const float* Wr   = (const float*)d_in[3];
    const float* aw   = (const float*)d_in[4];
    float*       out  = (float*)d_out;

    gat_gemm<<<dim3(32, 8), 256>>>(h, Wl, Wr);

    size_t smem = SMEM_FLOATS * sizeof(float);       // ~74 KB
    cudaFuncSetAttribute(gat_main, cudaFuncAttributeMaxDynamicSharedMemorySize, (int)smem);
    gat_main<<<dim3(2, N_NODES / TI), 1024, smem>>>(adj, aw, out);

    gat_combine<<<N_NODES / TI, 1024>>>(out);
}

// round 14
// speedup vs baseline: 1.0361x; 1.0361x over previous
#include <cuda_runtime.h>
#include <cuda_bf16.h>
#include <math.h>

#define N_NODES 1024
#define IN_F    256
#define OUT_F   128   // H*NH
#define TI      8     // target nodes per i-group
#define JHALF   512   // source nodes per block

// GL4[f][j] = float4 over heads (gl[j][hh*32+f], hh=0..3); row 32 = pad
__device__ float4 GL4[33 * N_NODES];
// GRD[opair][j] = (gr[2p][j], gr[2p+1][j])
__device__ float2 GRD[64 * N_NODES];
// gr natural layout [j][o]
__device__ float GRN[N_NODES * OUT_F];
// partial aggregation scratch
__device__ float PNUM[256][1024];
__device__ float PDEN[256][32];

// ---------------------------------------------------------------------------
// Packed fp32x2 helpers
// ---------------------------------------------------------------------------
__device__ __forceinline__ float2 fadd2(float2 a, float2 b) {
    float2 r;
    asm("add.rn.f32x2 %0, %1, %2;"
        : "=l"(*(unsigned long long*)&r)
        : "l"(*(const unsigned long long*)&a),
          "l"(*(const unsigned long long*)&b));
    return r;
}
__device__ __forceinline__ float2 ffma2(float2 a, float2 b, float2 c) {
    float2 r;
    asm("fma.rn.f32x2 %0, %1, %2, %3;"
        : "=l"(*(unsigned long long*)&r)
        : "l"(*(const unsigned long long*)&a),
          "l"(*(const unsigned long long*)&b),
          "l"(*(const unsigned long long*)&c));
    return r;
}
__device__ __forceinline__ float2 pack2(float x, float y) {
    float2 r;
    asm("mov.b64 %0, {%1, %2};"
        : "=l"(*(unsigned long long*)&r) : "f"(x), "f"(y));
    return r;
}

// ---------------------------------------------------------------------------
// Kernel A: tiled GEMM, ILP-first. grid (16 j-chunks, 8 o-groups) = 128 blocks,
// 256 threads. Tile = 64 j x 32 o-slots, k chunks of 64, reg double-buffered.
// Thread = (o-quad oq, j-pair jp) -> 8 outputs, 4 independent FFMA2 chains.
// Per k: LDS.128 (o-quad) + LDS.64 (j-pair, broadcast) + 4 FFMA2.
// o-groups 0..3 -> gl (W rows permuted: slot s = hh*8+fl); 4..7 -> gr.
// ---------------------------------------------------------------------------
#define HS3 66   // hs row stride (floats): 66*4 = 264 B, 8B-aligned
#define WS3 36   // ws row stride (floats): 36*4 = 144 B, 16B-aligned
#define SS3 65   // staging stride

__global__ void __launch_bounds__(256) gat_gemm(
    const float* __restrict__ h,
    const float* __restrict__ Wl,
    const float* __restrict__ Wr)
{
    __shared__ float hs[64 * HS3];   // [k][j_loc]
    __shared__ float ws[64 * WS3];   // [k][o_slot]

    const int t  = threadIdx.x;
    const int bx = blockIdx.x;             // j-chunk (0..15)
    const int by = blockIdx.y;             // o-group (0..7)
    const int j0 = bx * 64;
    const bool is_gl = (by < 4);

    // compute roles
    const int oq = t & 7;                  // o slots 4oq .. 4oq+3
    const int jp = t >> 3;                 // j_loc 2jp, 2jp+1

    // load roles
    const int wls = t >> 3;                // W slot 0..31
    const int wlk = (t & 7) * 8;           // 8 floats of k
    const int hls = t >> 2;                // h j 0..63
    const int hlk = (t & 3) * 16;          // 16 floats of k

    int wrow;
    const float* __restrict__ Wsrc;
    if (is_gl) { wrow = ((wls >> 3) << 5) + (by << 3) + (wls & 7); Wsrc = Wl; }
    else       { wrow = ((by - 4) << 5) + wls;                     Wsrc = Wr; }
    const float* __restrict__ wptr = Wsrc + wrow * IN_F + wlk;
    const float* __restrict__ hptr = h + (j0 + hls) * IN_F + hlk;

    float rw[8], rh[16];
#pragma unroll
    for (int u = 0; u < 2; u++) *(float4*)&rw[u * 4] = *(const float4*)&wptr[u * 4];
#pragma unroll
    for (int u = 0; u < 4; u++) *(float4*)&rh[u * 4] = *(const float4*)&hptr[u * 4];

    // accp[jl*2 + op] covers o = 4oq + 2op + {0,1}, j = 2jp + jl
    float2 accp[4];
#pragma unroll
    for (int v = 0; v < 4; v++) accp[v] = make_float2(0.f, 0.f);

    for (int c = 0; c < 4; c++) {
        __syncthreads();
#pragma unroll
        for (int u = 0; u < 8; u++)  ws[(wlk + u) * WS3 + wls] = rw[u];
#pragma unroll
        for (int u = 0; u < 16; u++) hs[(hlk + u) * HS3 + hls] = rh[u];
        __syncthreads();
        if (c < 3) {
            const float* wn = wptr + (c + 1) * 64;
            const float* hn = hptr + (c + 1) * 64;
#pragma unroll
            for (int u = 0; u < 2; u++) *(float4*)&rw[u * 4] = *(const float4*)&wn[u * 4];
#pragma unroll
            for (int u = 0; u < 4; u++) *(float4*)&rh[u * 4] = *(const float4*)&hn[u * 4];
        }
#pragma unroll 16
        for (int k = 0; k < 64; k++) {
            float4 wv = *(const float4*)&ws[k * WS3 + 4 * oq];   // 1 wavefront
            float2 hv = *(const float2*)&hs[k * HS3 + 2 * jp];   // broadcast
            float2 w01 = make_float2(wv.x, wv.y);
            float2 w23 = make_float2(wv.z, wv.w);
            float2 h0 = pack2(hv.x, hv.x);
            float2 h1 = pack2(hv.y, hv.y);
            accp[0] = ffma2(h0, w01, accp[0]);
            accp[1] = ffma2(h0, w23, accp[1]);
            accp[2] = ffma2(h1, w01, accp[2]);
            accp[3] = ffma2(h1, w23, accp[3]);
        }
    }

    if (is_gl) {
        // stage [slot][j_loc], then emit GL4 float4 over hh (coalesced)
        __syncthreads();
#pragma unroll
        for (int jl = 0; jl < 2; jl++)
#pragma unroll
            for (int op = 0; op < 2; op++) {
                hs[(4 * oq + 2 * op    ) * SS3 + 2 * jp + jl] = accp[jl * 2 + op].x;
                hs[(4 * oq + 2 * op + 1) * SS3 + 2 * jp + jl] = accp[jl * 2 + op].y;
            }
        __syncthreads();
        const int fl = t >> 5, jl = t & 31;      // fl 0..7
        const int f  = (by << 3) + fl;
#pragma unroll
        for (int half = 0; half < 2; half++) {
            int jc = jl + half * 32;
            float4 g;
            g.x = hs[( 0 + fl) * SS3 + jc];
            g.y = hs[( 8 + fl) * SS3 + jc];
            g.z = hs[(16 + fl) * SS3 + jc];
            g.w = hs[(24 + fl) * SS3 + jc];
            GL4[(f << 10) + j0 + jc] = g;
        }
    } else {
        const int og0 = (by - 4) << 5;
#pragma unroll
        for (int jl = 0; jl < 2; jl++) {
            int j = j0 + 2 * jp + jl;
#pragma unroll
            for (int op = 0; op < 2; op++) {
                float2 v = accp[jl * 2 + op];
                *(float2*)&GRN[(j << 7) + og0 + 4 * oq + 2 * op] = v;
                GRD[(((og0 >> 1) + 2 * oq + op) << 10) + j] = v;
            }
        }
    }
}

// ---------------------------------------------------------------------------
// Kernel B: grid (2 j-halves, 128 i-groups), 1024 threads.
// Thread = (j, f-half); f-halves share a warp (lane halves) and combine via
// shfl.xor(16). Block emits PARTIAL num/den to global scratch (no max-pass
// softmax; partial sums compose exactly).
// ---------------------------------------------------------------------------
#define OFF_GRS  16384
#define OFF_RED  (OFF_GRS + 1024)
#define OFF_DOTR (OFF_RED + 1056)
#define OFF_CW   (OFF_DOTR + 32)
#define SMEM_FLOATS (OFF_CW + 64)

__global__ void __launch_bounds__(1024, 1) gat_main(
    const int*   __restrict__ adj,
    const float* __restrict__ attn_w,
    float*       __restrict__ out_unused)
{
    extern __shared__ float sm[];
    float4* a4     = (float4*)sm;            // 8 rows x 512 float4 (p values)
    float*  grs    = sm + OFF_GRS;           // [o][ii 0..7]
    float*  red    = sm + OFF_RED;           // 32 warps x 33
    float*  dotr_s = sm + OFF_DOTR;          // 32
    float2* cw     = (float2*)(sm + OFF_CW);

    const int t     = threadIdx.x;
    const int lane  = t & 31;
    const int warp  = t >> 5;
    const int jhb   = blockIdx.x;            // j-half
    const int ib    = blockIdx.y;            // i-group
    const int i0    = ib * TI;
    const int jbase = jhb * JHALF;
    const int jl    = lane & 15;
    const int fh    = lane >> 4;             // f-half AND ii-half role
    const int jloc  = (warp << 4) + jl;      // 0..511
    const int j     = jbase + jloc;          // global source node
    const int sidx  = ib * 2 + jhb;

    if (t < 32) { float w = attn_w[t]; cw[t] = make_float2(0.6f * w, 0.4f * w); }
    { int ii = t >> 7, oo = t & 127; grs[(oo << 3) + ii] = GRN[(i0 + ii) * OUT_F + oo]; }

    unsigned am = 0;   // 4 bits for ii in this thread's half
#pragma unroll
    for (int iil = 0; iil < 4; iil++)
        am |= (adj[(i0 + (fh << 2) + iil) * N_NODES + j] != 0) ? (1u << iil) : 0u;
    __syncthreads();

    // warp 0: dotr[ii][hh] = sum_f 0.6*w_f * gr[i0+ii][hh*32+f]
    if (t < 32) {
        int ii = t >> 2, hh = t & 3;
        float s = 0.f;
#pragma unroll 8
        for (int f = 0; f < 32; f++)
            s += cw[f].x * grs[(((hh << 5) + f) << 3) + ii];
        dotr_s[t] = s;   // index q = ii*4 + hh
    }

    // -------- Phase 1: half the f's per thread, all 8 ii --------
    float acc[32];               // [ii*4 + hh]
#pragma unroll
    for (int q = 0; q < 32; q++) acc[q] = 0.f;
    float dl[4] = {0.f, 0.f, 0.f, 0.f};

    const float4* grs4 = (const float4*)grs;
    const int fbase = fh << 4;
    for (int fi = 0; fi < 16; fi++) {
        int f = fbase + fi;
        float4 ga = GL4[(f << 10) + j];
        float2 c = cw[f];
        dl[0] = fmaf(c.x, ga.x, dl[0]);
        dl[1] = fmaf(c.x, ga.y, dl[1]);
        dl[2] = fmaf(c.x, ga.z, dl[2]);
        dl[3] = fmaf(c.x, ga.w, dl[3]);
        float gaa[4] = {ga.x, ga.y, ga.z, ga.w};
#pragma unroll
        for (int hh = 0; hh < 4; hh++) {
            int o = (hh << 5) + f;
            float4 g0 = grs4[o * 2];         // ii 0..3
            float4 g1 = grs4[o * 2 + 1];     // ii 4..7
            float2 gl2 = pack2(gaa[hh], gaa[hh]);
            float2 x01 = fadd2(gl2, pack2(g0.x, g0.y));
            float2 x23 = fadd2(gl2, pack2(g0.z, g0.w));
            float2 x45 = fadd2(gl2, pack2(g1.x, g1.y));
            float2 x67 = fadd2(gl2, pack2(g1.z, g1.w));
            acc[ 0 + hh] = fmaf(c.y, fabsf(x01.x), acc[ 0 + hh]);
            acc[ 4 + hh] = fmaf(c.y, fabsf(x01.y), acc[ 4 + hh]);
            acc[ 8 + hh] = fmaf(c.y, fabsf(x23.x), acc[ 8 + hh]);
            acc[12 + hh] = fmaf(c.y, fabsf(x23.y), acc[12 + hh]);
            acc[16 + hh] = fmaf(c.y, fabsf(x45.x), acc[16 + hh]);
            acc[20 + hh] = fmaf(c.y, fabsf(x45.y), acc[20 + hh]);
            acc[24 + hh] = fmaf(c.y, fabsf(x67.x), acc[24 + hh]);
            acc[28 + hh] = fmaf(c.y, fabsf(x67.y), acc[28 + hh]);
        }
    }
    // combine f-halves: lane l <-> l^16 hold the two partial sums for same j
#pragma unroll
    for (int q = 0; q < 32; q++) acc[q] += __shfl_xor_sync(0xffffffffu, acc[q], 16);
#pragma unroll
    for (int hh = 0; hh < 4; hh++) dl[hh] += __shfl_xor_sync(0xffffffffu, dl[hh], 16);
    __syncthreads();   // dotr_s visible

    // -------- Phase 2: each lane-half finalizes its 4 ii --------
    float p[16];       // [iil*4 + hh], ii = fh*4 + iil
    {
        const int qb = fh << 4;
#pragma unroll
        for (int iil = 0; iil < 4; iil++) {
            bool m = (am >> iil) & 1u;
#pragma unroll
            for (int hh = 0; hh < 4; hh++) {
                float e = acc[qb + iil * 4 + hh] + dl[hh]
                        + dotr_s[(((fh << 2) + iil) << 2) + hh];
                p[iil * 4 + hh] = m ? __expf(e) : 0.f;
            }
        }
        // store p: row = hh*2 + fh, float4 over iil
#pragma unroll
        for (int hh = 0; hh < 4; hh++) {
            float4 v = make_float4(p[hh], p[4 + hh], p[8 + hh], p[12 + hh]);
            a4[(((hh << 1) + fh) << 9) + jloc] = v;
        }
    }
    // partial den: reduce over 16 j within each half-warp
#pragma unroll
    for (int qq = 0; qq < 16; qq++) {
        float v = p[qq];
#pragma unroll
        for (int d = 8; d; d >>= 1) v += __shfl_xor_sync(0xffffffffu, v, d);
        if (jl == 0) red[warp * 33 + (fh << 4) + qq] = v;
    }
    __syncthreads();   // p stores + red complete
    if (t < 32) {
        float s = 0.f;
#pragma unroll
        for (int w8 = 0; w8 < 32; w8++) s += red[w8 * 33 + t];
        PDEN[sidx][t] = s;     // q = ii*4 + hh
    }

    // -------- Phase 3: partial aggregation over this j-half --------
    const int opair = t >> 4;            // 0..63
    const int ihp   = (t >> 3) & 1;      // ii-half
    const int c     = t & 7;             // j-partition
    const int hh3   = opair >> 4;
    float2 accp[4];
#pragma unroll
    for (int v = 0; v < 4; v++) accp[v] = make_float2(0.f, 0.f);

    const float4* prow = a4 + (((hh3 << 1) + ihp) << 9);
    const float2* grp  = GRD + (opair << 10) + jbase;
#pragma unroll 4
    for (int g = 0; g < 64; g++) {
        int jl3 = (g << 3) + c;
        float4 pv = prow[jl3];           // 4 ii of this half
        float2 gr = grp[jl3];            // both o's of the pair
        float2 p01 = make_float2(pv.x, pv.y);
        float2 p23 = make_float2(pv.z, pv.w);
        float2 gx2 = pack2(gr.x, gr.x);
        float2 gy2 = pack2(gr.y, gr.y);
        accp[0] = ffma2(p01, gx2, accp[0]);
        accp[1] = ffma2(p23, gx2, accp[1]);
        accp[2] = ffma2(p01, gy2, accp[2]);
        accp[3] = ffma2(p23, gy2, accp[3]);
    }
    __syncthreads();                     // all a4 reads complete

    float a8[8] = {accp[0].x, accp[0].y, accp[1].x, accp[1].y,
                   accp[2].x, accp[2].y, accp[3].x, accp[3].y};
    float* part = sm;                    // [t][8] padded to 9
#pragma unroll
    for (int v = 0; v < 8; v++) part[t * 9 + v] = a8[v];
    __syncthreads();

    {
        int o2 = t & 127, ii2 = t >> 7;
        int op = o2 >> 1, oi = o2 & 1, ihq = ii2 >> 2, iil = ii2 & 3;
        float s = 0.f;
#pragma unroll
        for (int cc = 0; cc < 8; cc++)
            s += part[((op << 4) + (ihq << 3) + cc) * 9 + (oi << 2) + iil];
        PNUM[sidx][(ii2 << 7) + o2] = s;
    }
}

// ---------------------------------------------------------------------------
// Kernel C: combine the two j-half partials, normalize, ELU, write out.
// ---------------------------------------------------------------------------
__global__ void __launch_bounds__(1024) gat_combine(float* __restrict__ out)
{
    const int b = blockIdx.x;            // i-group
    const int t = threadIdx.x;
    const int ii2 = t >> 7, o2 = t & 127;
    float num = PNUM[b * 2][t] + PNUM[b * 2 + 1][t];
    int q = (ii2 << 2) + (o2 >> 5);
    float den = PDEN[b * 2][q] + PDEN[b * 2 + 1][q];
    float s = num / den;
    out[(b * TI + ii2) * OUT_F + o2] = (s > 0.f) ? s : expm1f(s);
}

// ---------------------------------------------------------------------------
extern "C" void kernel_launch(void* const* d_in, const int* in_sizes, int n_in,
                              void* d_out, int out_size)
{
    const float* h    = (const float*)d_in[0];
    const int*   adj  = (const int*)  d_in[1];
    const float* Wl   = (const float*)d_in[2];
    const float* Wr   = (const float*)d_in[3];
    const float* aw   = (const float*)d_in[4];
    float*       out  = (float*)d_out;

    gat_gemm<<<dim3(16, 8), 256>>>(h, Wl, Wr);

    size_t smem = SMEM_FLOATS * sizeof(float);       // ~74 KB
    cudaFuncSetAttribute(gat_main, cudaFuncAttributeMaxDynamicSharedMemorySize, (int)smem);
    gat_main<<<dim3(2, N_NODES / TI), 1024, smem>>>(adj, aw, out);

    gat_combine<<<N_NODES / TI, 1024>>>(out);
}

// round 16
// speedup vs baseline: 1.0692x; 1.0320x over previous
#include <cuda_runtime.h>
#include <cuda_bf16.h>
#include <math.h>

#define N_NODES 1024
#define IN_F    256
#define OUT_F   128   // H*NH
#define TI      8     // target nodes per i-group
#define JHALF   512   // source nodes per block

// GL4[f][j] = float4 over heads (gl[j][hh*32+f], hh=0..3); row 32 = pad
__device__ float4 GL4[33 * N_NODES];
// GRD[opair][j] = (gr[2p][j], gr[2p+1][j])
__device__ float2 GRD[64 * N_NODES];
// gr natural layout [j][o]
__device__ float GRN[N_NODES * OUT_F];
// partial aggregation scratch
__device__ float PNUM[256][1024];
__device__ float PDEN[256][32];

// ---------------------------------------------------------------------------
// Packed fp32x2 helpers
// ---------------------------------------------------------------------------
__device__ __forceinline__ float2 fadd2(float2 a, float2 b) {
    float2 r;
    asm("add.rn.f32x2 %0, %1, %2;"
        : "=l"(*(unsigned long long*)&r)
        : "l"(*(const unsigned long long*)&a),
          "l"(*(const unsigned long long*)&b));
    return r;
}
__device__ __forceinline__ float2 ffma2(float2 a, float2 b, float2 c) {
    float2 r;
    asm("fma.rn.f32x2 %0, %1, %2, %3;"
        : "=l"(*(unsigned long long*)&r)
        : "l"(*(const unsigned long long*)&a),
          "l"(*(const unsigned long long*)&b),
          "l"(*(const unsigned long long*)&c));
    return r;
}
__device__ __forceinline__ float2 pack2(float x, float y) {
    float2 r;
    asm("mov.b64 %0, {%1, %2};"
        : "=l"(*(unsigned long long*)&r) : "f"(x), "f"(y));
    return r;
}

// ---------------------------------------------------------------------------
// Kernel A v5: grid (16 j-chunks, 8 o-groups) = 128 blocks, 256 threads.
// Whole k=256 resident: ws[32 slots][260], hs[64 j][260] (row-major, odd-x4
// stride). Fill via float4 LDG->STS.128, ONE sync. Inner: per 4-k group,
// 4 w-row LDS.128 + 2 h-row LDS.128 + 16 FFMA2 packed over k-pairs.
// Thread = (oq, jp): slots {oq,oq+8,oq+16,oq+24} x j {2jp, 2jp+1}.
// o-groups 0..3 -> gl (slot s: head=s>>3, f=by*8+(s&7)) -> GL4 direct write;
// o-groups 4..7 -> gr (slot s -> row og0+s) -> GRN/GRD scalar writes.
// ---------------------------------------------------------------------------
#define RS5 260            // row stride in floats (multiple of 4, 260%32=4)
#define GEMM_SMEM_FLOATS ((32 + 64) * RS5)

__global__ void __launch_bounds__(256) gat_gemm(
    const float* __restrict__ h,
    const float* __restrict__ Wl,
    const float* __restrict__ Wr)
{
    extern __shared__ float smg[];
    float* ws = smg;              // [slot][k]
    float* hs = smg + 32 * RS5;   // [j_loc][k]

    const int t  = threadIdx.x;
    const int bx = blockIdx.x;             // j-chunk (0..15)
    const int by = blockIdx.y;             // o-group (0..7)
    const int j0 = bx * 64;
    const bool is_gl = (by < 4);

    const int oq = t & 7;                  // slot base
    const int jp = t >> 3;                 // j pair (0..31)

    // ---- fill ws: 32 rows x 64 float4 ----
    const float* __restrict__ Wsrc = is_gl ? Wl : Wr;
    const int og0 = is_gl ? 0 : ((by - 4) << 5);
#pragma unroll
    for (int it = 0; it < 8; it++) {
        int idx = t + it * 256;            // 0..2047
        int row = idx >> 6, kq = idx & 63;
        int wrow = is_gl ? (((row >> 3) << 5) + (by << 3) + (row & 7))
                         : (og0 + row);
        *(float4*)&ws[row * RS5 + kq * 4] =
            *(const float4*)&Wsrc[wrow * IN_F + kq * 4];
    }
    // ---- fill hs: 64 rows x 64 float4 ----
#pragma unroll
    for (int it = 0; it < 16; it++) {
        int idx = t + it * 256;            // 0..4095
        int row = idx >> 6, kq = idx & 63;
        *(float4*)&hs[row * RS5 + kq * 4] =
            *(const float4*)&h[(j0 + row) * IN_F + kq * 4];
    }
    __syncthreads();

    const float* wp0 = ws + (oq     ) * RS5;
    const float* wp1 = ws + (oq +  8) * RS5;
    const float* wp2 = ws + (oq + 16) * RS5;
    const float* wp3 = ws + (oq + 24) * RS5;
    const float* hp0 = hs + (2 * jp    ) * RS5;
    const float* hp1 = hs + (2 * jp + 1) * RS5;

    float2 acc[8];   // [v*2 + jl], packed over (even k, odd k)
#pragma unroll
    for (int v = 0; v < 8; v++) acc[v] = make_float2(0.f, 0.f);

#pragma unroll 8
    for (int kg = 0; kg < 64; kg++) {
        float4 w0 = *(const float4*)&wp0[kg * 4];
        float4 w1 = *(const float4*)&wp1[kg * 4];
        float4 w2 = *(const float4*)&wp2[kg * 4];
        float4 w3 = *(const float4*)&wp3[kg * 4];
        float4 h0 = *(const float4*)&hp0[kg * 4];
        float4 h1 = *(const float4*)&hp1[kg * 4];
        float2 h0lo = make_float2(h0.x, h0.y), h0hi = make_float2(h0.z, h0.w);
        float2 h1lo = make_float2(h1.x, h1.y), h1hi = make_float2(h1.z, h1.w);
        acc[0] = ffma2(make_float2(w0.x, w0.y), h0lo, acc[0]);
        acc[1] = ffma2(make_float2(w0.x, w0.y), h1lo, acc[1]);
        acc[2] = ffma2(make_float2(w1.x, w1.y), h0lo, acc[2]);
        acc[3] = ffma2(make_float2(w1.x, w1.y), h1lo, acc[3]);
        acc[4] = ffma2(make_float2(w2.x, w2.y), h0lo, acc[4]);
        acc[5] = ffma2(make_float2(w2.x, w2.y), h1lo, acc[5]);
        acc[6] = ffma2(make_float2(w3.x, w3.y), h0lo, acc[6]);
        acc[7] = ffma2(make_float2(w3.x, w3.y), h1lo, acc[7]);
        acc[0] = ffma2(make_float2(w0.z, w0.w), h0hi, acc[0]);
        acc[1] = ffma2(make_float2(w0.z, w0.w), h1hi, acc[1]);
        acc[2] = ffma2(make_float2(w1.z, w1.w), h0hi, acc[2]);
        acc[3] = ffma2(make_float2(w1.z, w1.w), h1hi, acc[3]);
        acc[4] = ffma2(make_float2(w2.z, w2.w), h0hi, acc[4]);
        acc[5] = ffma2(make_float2(w2.z, w2.w), h1hi, acc[5]);
        acc[6] = ffma2(make_float2(w3.z, w3.w), h0hi, acc[6]);
        acc[7] = ffma2(make_float2(w3.z, w3.w), h1hi, acc[7]);
    }

    // scalar results sc[v][jl]
    float sc[4][2];
#pragma unroll
    for (int v = 0; v < 4; v++)
#pragma unroll
        for (int jl = 0; jl < 2; jl++)
            sc[v][jl] = acc[v * 2 + jl].x + acc[v * 2 + jl].y;

    if (is_gl) {
        const int f = (by << 3) + oq;
#pragma unroll
        for (int jl = 0; jl < 2; jl++) {
            int j = j0 + 2 * jp + jl;
            GL4[(f << 10) + j] = make_float4(sc[0][jl], sc[1][jl], sc[2][jl], sc[3][jl]);
        }
    } else {
        float* grdf = (float*)GRD;
#pragma unroll
        for (int jl = 0; jl < 2; jl++) {
            int j = j0 + 2 * jp + jl;
#pragma unroll
            for (int v = 0; v < 4; v++) {
                int o = og0 + oq + 8 * v;
                GRN[(j << 7) + o] = sc[v][jl];
                grdf[((((o >> 1) << 10) + j) << 1) + (o & 1)] = sc[v][jl];
            }
        }
    }
}

// ---------------------------------------------------------------------------
// Kernel B: grid (2 j-halves, 128 i-groups), 1024 threads.
// Thread = (j, f-half); f-halves share a warp (lane halves) and combine via
// shfl.xor(16). Block emits PARTIAL num/den to global scratch (no max-pass
// softmax; partial sums compose exactly).
// ---------------------------------------------------------------------------
#define OFF_GRS  16384
#define OFF_RED  (OFF_GRS + 1024)
#define OFF_DOTR (OFF_RED + 1056)
#define OFF_CW   (OFF_DOTR + 32)
#define SMEM_FLOATS (OFF_CW + 64)

__global__ void __launch_bounds__(1024, 1) gat_main(
    const int*   __restrict__ adj,
    const float* __restrict__ attn_w,
    float*       __restrict__ out_unused)
{
    extern __shared__ float sm[];
    float4* a4     = (float4*)sm;            // 8 rows x 512 float4 (p values)
    float*  grs    = sm + OFF_GRS;           // [o][ii 0..7]
    float*  red    = sm + OFF_RED;           // 32 warps x 33
    float*  dotr_s = sm + OFF_DOTR;          // 32
    float2* cw     = (float2*)(sm + OFF_CW);

    const int t     = threadIdx.x;
    const int lane  = t & 31;
    const int warp  = t >> 5;
    const int jhb   = blockIdx.x;            // j-half
    const int ib    = blockIdx.y;            // i-group
    const int i0    = ib * TI;
    const int jbase = jhb * JHALF;
    const int jl    = lane & 15;
    const int fh    = lane >> 4;             // f-half AND ii-half role
    const int jloc  = (warp << 4) + jl;      // 0..511
    const int j     = jbase + jloc;          // global source node
    const int sidx  = ib * 2 + jhb;

    if (t < 32) { float w = attn_w[t]; cw[t] = make_float2(0.6f * w, 0.4f * w); }
    { int ii = t >> 7, oo = t & 127; grs[(oo << 3) + ii] = GRN[(i0 + ii) * OUT_F + oo]; }

    unsigned am = 0;   // 4 bits for ii in this thread's half
#pragma unroll
    for (int iil = 0; iil < 4; iil++)
        am |= (adj[(i0 + (fh << 2) + iil) * N_NODES + j] != 0) ? (1u << iil) : 0u;
    __syncthreads();

    // warp 0: dotr[ii][hh] = sum_f 0.6*w_f * gr[i0+ii][hh*32+f]
    if (t < 32) {
        int ii = t >> 2, hh = t & 3;
        float s = 0.f;
#pragma unroll 8
        for (int f = 0; f < 32; f++)
            s += cw[f].x * grs[(((hh << 5) + f) << 3) + ii];
        dotr_s[t] = s;   // index q = ii*4 + hh
    }

    // -------- Phase 1: half the f's per thread, all 8 ii --------
    float acc[32];               // [ii*4 + hh]
#pragma unroll
    for (int q = 0; q < 32; q++) acc[q] = 0.f;
    float dl[4] = {0.f, 0.f, 0.f, 0.f};

    const float4* grs4 = (const float4*)grs;
    const int fbase = fh << 4;
    for (int fi = 0; fi < 16; fi++) {
        int f = fbase + fi;
        float4 ga = GL4[(f << 10) + j];
        float2 c = cw[f];
        dl[0] = fmaf(c.x, ga.x, dl[0]);
        dl[1] = fmaf(c.x, ga.y, dl[1]);
        dl[2] = fmaf(c.x, ga.z, dl[2]);
        dl[3] = fmaf(c.x, ga.w, dl[3]);
        float gaa[4] = {ga.x, ga.y, ga.z, ga.w};
#pragma unroll
        for (int hh = 0; hh < 4; hh++) {
            int o = (hh << 5) + f;
            float4 g0 = grs4[o * 2];         // ii 0..3
            float4 g1 = grs4[o * 2 + 1];     // ii 4..7
            float2 gl2 = pack2(gaa[hh], gaa[hh]);
            float2 x01 = fadd2(gl2, pack2(g0.x, g0.y));
            float2 x23 = fadd2(gl2, pack2(g0.z, g0.w));
            float2 x45 = fadd2(gl2, pack2(g1.x, g1.y));
            float2 x67 = fadd2(gl2, pack2(g1.z, g1.w));
            acc[ 0 + hh] = fmaf(c.y, fabsf(x01.x), acc[ 0 + hh]);
            acc[ 4 + hh] = fmaf(c.y, fabsf(x01.y), acc[ 4 + hh]);
            acc[ 8 + hh] = fmaf(c.y, fabsf(x23.x), acc[ 8 + hh]);
            acc[12 + hh] = fmaf(c.y, fabsf(x23.y), acc[12 + hh]);
            acc[16 + hh] = fmaf(c.y, fabsf(x45.x), acc[16 + hh]);
            acc[20 + hh] = fmaf(c.y, fabsf(x45.y), acc[20 + hh]);
            acc[24 + hh] = fmaf(c.y, fabsf(x67.x), acc[24 + hh]);
            acc[28 + hh] = fmaf(c.y, fabsf(x67.y), acc[28 + hh]);
        }
    }
    // combine f-halves: lane l <-> l^16 hold the two partial sums for same j
#pragma unroll
    for (int q = 0; q < 32; q++) acc[q] += __shfl_xor_sync(0xffffffffu, acc[q], 16);
#pragma unroll
    for (int hh = 0; hh < 4; hh++) dl[hh] += __shfl_xor_sync(0xffffffffu, dl[hh], 16);
    __syncthreads();   // dotr_s visible

    // -------- Phase 2: each lane-half finalizes its 4 ii --------
    float p[16];       // [iil*4 + hh], ii = fh*4 + iil
    {
        const int qb = fh << 4;
#pragma unroll
        for (int iil = 0; iil < 4; iil++) {
            bool m = (am >> iil) & 1u;
#pragma unroll
            for (int hh = 0; hh < 4; hh++) {
                float e = acc[qb + iil * 4 + hh] + dl[hh]
                        + dotr_s[(((fh << 2) + iil) << 2) + hh];
                p[iil * 4 + hh] = m ? __expf(e) : 0.f;
            }
        }
        // store p: row = hh*2 + fh, float4 over iil
#pragma unroll
        for (int hh = 0; hh < 4; hh++) {
            float4 v = make_float4(p[hh], p[4 + hh], p[8 + hh], p[12 + hh]);
            a4[(((hh << 1) + fh) << 9) + jloc] = v;
        }
    }
    // partial den: reduce over 16 j within each half-warp
#pragma unroll
    for (int qq = 0; qq < 16; qq++) {
        float v = p[qq];
#pragma unroll
        for (int d = 8; d; d >>= 1) v += __shfl_xor_sync(0xffffffffu, v, d);
        if (jl == 0) red[warp * 33 + (fh << 4) + qq] = v;
    }
    __syncthreads();   // p stores + red complete
    if (t < 32) {
        float s = 0.f;
#pragma unroll
        for (int w8 = 0; w8 < 32; w8++) s += red[w8 * 33 + t];
        PDEN[sidx][t] = s;     // q = ii*4 + hh
    }

    // -------- Phase 3: partial aggregation over this j-half --------
    const int opair = t >> 4;            // 0..63
    const int ihp   = (t >> 3) & 1;      // ii-half
    const int c     = t & 7;             // j-partition
    const int hh3   = opair >> 4;
    float2 accp[4];
#pragma unroll
    for (int v = 0; v < 4; v++) accp[v] = make_float2(0.f, 0.f);

    const float4* prow = a4 + (((hh3 << 1) + ihp) << 9);
    const float2* grp  = GRD + (opair << 10) + jbase;
#pragma unroll 4
    for (int g = 0; g < 64; g++) {
        int jl3 = (g << 3) + c;
        float4 pv = prow[jl3];           // 4 ii of this half
        float2 gr = grp[jl3];            // both o's of the pair
        float2 p01 = make_float2(pv.x, pv.y);
        float2 p23 = make_float2(pv.z, pv.w);
        float2 gx2 = pack2(gr.x, gr.x);
        float2 gy2 = pack2(gr.y, gr.y);
        accp[0] = ffma2(p01, gx2, accp[0]);
        accp[1] = ffma2(p23, gx2, accp[1]);
        accp[2] = ffma2(p01, gy2, accp[2]);
        accp[3] = ffma2(p23, gy2, accp[3]);
    }
    __syncthreads();                     // all a4 reads complete

    float a8[8] = {accp[0].x, accp[0].y, accp[1].x, accp[1].y,
                   accp[2].x, accp[2].y, accp[3].x, accp[3].y};
    float* part = sm;                    // [t][8] padded to 9
#pragma unroll
    for (int v = 0; v < 8; v++) part[t * 9 + v] = a8[v];
    __syncthreads();

    {
        int o2 = t & 127, ii2 = t >> 7;
        int op = o2 >> 1, oi = o2 & 1, ihq = ii2 >> 2, iil = ii2 & 3;
        float s = 0.f;
#pragma unroll
        for (int cc = 0; cc < 8; cc++)
            s += part[((op << 4) + (ihq << 3) + cc) * 9 + (oi << 2) + iil];
        PNUM[sidx][(ii2 << 7) + o2] = s;
    }
}

// ---------------------------------------------------------------------------
// Kernel C: combine the two j-half partials, normalize, ELU, write out.
// ---------------------------------------------------------------------------
__global__ void __launch_bounds__(1024) gat_combine(float* __restrict__ out)
{
    const int b = blockIdx.x;            // i-group
    const int t = threadIdx.x;
    const int ii2 = t >> 7, o2 = t & 127;
    float num = PNUM[b * 2][t] + PNUM[b * 2 + 1][t];
    int q = (ii2 << 2) + (o2 >> 5);
    float den = PDEN[b * 2][q] + PDEN[b * 2 + 1][q];
    float s = num / den;
    out[(b * TI + ii2) * OUT_F + o2] = (s > 0.f) ? s : expm1f(s);
}

// ---------------------------------------------------------------------------
extern "C" void kernel_launch(void* const* d_in, const int* in_sizes, int n_in,
                              void* d_out, int out_size)
{
    const float* h    = (const float*)d_in[0];
    const int*   adj  = (const int*)  d_in[1];
    const float* Wl   = (const float*)d_in[2];
    const float* Wr   = (const float*)d_in[3];
    const float* aw   = (const float*)d_in[4];
    float*       out  = (float*)d_out;

    size_t smg = GEMM_SMEM_FLOATS * sizeof(float);   // ~97.5 KB
    cudaFuncSetAttribute(gat_gemm, cudaFuncAttributeMaxDynamicSharedMemorySize, (int)smg);
    gat_gemm<<<dim3(16, 8), 256, smg>>>(h, Wl, Wr);

    size_t smem = SMEM_FLOATS * sizeof(float);       // ~74 KB
    cudaFuncSetAttribute(gat_main, cudaFuncAttributeMaxDynamicSharedMemorySize, (int)smem);
    gat_main<<<dim3(2, N_NODES / TI), 1024, smem>>>(adj, aw, out);

    gat_combine<<<N_NODES / TI, 1024>>>(out);
}